// round 7
// baseline (speedup 1.0000x reference)
#include <cuda_runtime.h>
#include <cstdint>

// SSIM loss fused single-pass: packed f32x2, 4 cols/thread, scaled-by-81
// identity, software-pipelined row loads, 64-row strips (single wave),
// forced 8 blocks/SM. x,y: (32,1,1024,1024) fp32 -> 1 float.

#define W 1024
#define H 1024
#define NIMG 32
#define TPB 128
#define CPT 4
#define COLS_PER_BLOCK (TPB * CPT)          // 512
#define GRID_X (W / COLS_PER_BLOCK)         // 2
#define ROWS_PER_STRIP 64
#define GRID_Y (H / ROWS_PER_STRIP)         // 16
#define NBLOCKS (GRID_X * GRID_Y * NIMG)    // 1024
#define NPIX ((double)NIMG * W * H)

__device__ float g_partials[NBLOCKS];
__device__ unsigned int g_count = 0;

// ---- packed f32x2 helpers (sm_103a) ----
__device__ __forceinline__ uint64_t pk(float lo, float hi) {
    uint64_t r;
    asm("mov.b64 %0, {%1, %2};" : "=l"(r) : "f"(lo), "f"(hi));
    return r;
}
__device__ __forceinline__ void upk(uint64_t v, float& lo, float& hi) {
    asm("mov.b64 {%0, %1}, %2;" : "=f"(lo), "=f"(hi) : "l"(v));
}
__device__ __forceinline__ uint64_t f2add(uint64_t a, uint64_t b) {
    uint64_t r;
    asm("add.rn.f32x2 %0, %1, %2;" : "=l"(r) : "l"(a), "l"(b));
    return r;
}
__device__ __forceinline__ uint64_t f2mul(uint64_t a, uint64_t b) {
    uint64_t r;
    asm("mul.rn.f32x2 %0, %1, %2;" : "=l"(r) : "l"(a), "l"(b));
    return r;
}
__device__ __forceinline__ uint64_t f2fma(uint64_t a, uint64_t b, uint64_t c) {
    uint64_t r;
    asm("fma.rn.f32x2 %0, %1, %2, %3;" : "=l"(r) : "l"(a), "l"(b), "l"(c));
    return r;
}
// packed negate: flip both sign bits, alu op with 64-bit immediate (no const reg)
__device__ __forceinline__ uint64_t f2neg(uint64_t a) {
    uint64_t r;
    asm("xor.b64 %0, %1, 0x8000000080000000;" : "=l"(r) : "l"(a));
    return r;
}

struct HRow { uint64_t v[8]; };  // [0,1]=hx [2,3]=hy [4,5]=h(x^2+y^2) [6,7]=h(xy)
struct Raw  { float4 vx, vy; float xl, xr, yl, yr; };

__device__ __forceinline__ Raw load_raw(const float* __restrict__ xp,
                                        const float* __restrict__ yp,
                                        int r, int c0) {
    Raw w;
    if ((unsigned)r < (unsigned)H) {
        const int base = r * W + c0;
        w.vx = *reinterpret_cast<const float4*>(xp + base);
        w.vy = *reinterpret_cast<const float4*>(yp + base);
        w.xl = (c0 > 0)     ? xp[base - 1] : 0.0f;
        w.xr = (c0 + 4 < W) ? xp[base + 4] : 0.0f;
        w.yl = (c0 > 0)     ? yp[base - 1] : 0.0f;
        w.yr = (c0 + 4 < W) ? yp[base + 4] : 0.0f;
    } else {
        w.vx = make_float4(0.f, 0.f, 0.f, 0.f);
        w.vy = make_float4(0.f, 0.f, 0.f, 0.f);
        w.xl = w.xr = w.yl = w.yr = 0.0f;
    }
    return w;
}

__device__ __forceinline__ void hrow_from(const Raw& w, HRow& h) {
    uint64_t PA0 = pk(w.xl, w.vx.x),   MA0 = pk(w.vx.x, w.vx.y);
    uint64_t PA1 = pk(w.vx.y, w.vx.z), MA1 = pk(w.vx.z, w.vx.w);
    uint64_t PA2 = pk(w.vx.w, w.xr);
    uint64_t PB0 = pk(w.yl, w.vy.x),   MB0 = pk(w.vy.x, w.vy.y);
    uint64_t PB1 = pk(w.vy.y, w.vy.z), MB1 = pk(w.vy.z, w.vy.w);
    uint64_t PB2 = pk(w.vy.w, w.yr);

    uint64_t S0  = f2fma(PA0, PA0, f2mul(PB0, PB0));
    uint64_t S1  = f2fma(PA1, PA1, f2mul(PB1, PB1));
    uint64_t S2  = f2fma(PA2, PA2, f2mul(PB2, PB2));
    uint64_t SM0 = f2fma(MA0, MA0, f2mul(MB0, MB0));
    uint64_t SM1 = f2fma(MA1, MA1, f2mul(MB1, MB1));
    uint64_t Q0  = f2mul(PA0, PB0);
    uint64_t Q1  = f2mul(PA1, PB1);
    uint64_t Q2  = f2mul(PA2, PB2);
    uint64_t QM0 = f2mul(MA0, MB0);
    uint64_t QM1 = f2mul(MA1, MB1);

    h.v[0] = f2add(f2add(PA0, MA0), PA1);
    h.v[1] = f2add(f2add(PA1, MA1), PA2);
    h.v[2] = f2add(f2add(PB0, MB0), PB1);
    h.v[3] = f2add(f2add(PB1, MB1), PB2);
    h.v[4] = f2add(f2add(S0, SM0), S1);
    h.v[5] = f2add(f2add(S1, SM1), S2);
    h.v[6] = f2add(f2add(Q0, QM0), Q1);
    h.v[7] = f2add(f2add(Q1, QM1), Q2);
}

// Consumes N (h of row r+1): S = A + N -> ssim; Aout = B + N; Bout = N.
__device__ __forceinline__ void step_math(const HRow& N,
                                          const HRow& A, const HRow& B,
                                          HRow& Aout, HRow& Bout,
                                          uint64_t C1S, uint64_t C2S,
                                          uint64_t EPSS, uint64_t TWO,
                                          uint64_t NINE, float& acc) {
    uint64_t S[8];
#pragma unroll
    for (int i = 0; i < 8; ++i) S[i] = f2add(A.v[i], N.v[i]);

#pragma unroll
    for (int half = 0; half < 2; ++half) {
        uint64_t sx  = S[half];
        uint64_t sy  = S[2 + half];
        uint64_t sss = S[4 + half];
        uint64_t sxy = S[6 + half];

        uint64_t ab  = f2mul(sx, sy);
        uint64_t t2  = f2fma(sx, sx, f2mul(sy, sy));
        uint64_t Aq  = f2fma(ab, TWO, C1S);                    // 2ab + 81C1
        uint64_t u   = f2fma(sxy, NINE, f2neg(ab));            // 9Sxy - ab
        uint64_t Bq  = f2fma(u, TWO, C2S);                     // 18Sxy - 2ab + 81C2
        uint64_t Cq  = f2add(t2, C1S);                         // t2 + 81C1
        uint64_t Dq  = f2add(f2fma(sss, NINE, C2S), f2neg(t2));// 9Sss - t2 + 81C2
        uint64_t num = f2mul(Aq, Bq);
        uint64_t den = f2fma(Cq, Dq, EPSS);

        float n0, n1, d0, d1;
        upk(num, n0, n1);
        upk(den, d0, d1);
        acc += __fdividef(fmaf(n0, d1, n1 * d0), d0 * d1);
    }

#pragma unroll
    for (int i = 0; i < 8; ++i) Aout.v[i] = f2add(B.v[i], N.v[i]);
    Bout = N;
}

__global__ __launch_bounds__(TPB, 8)
void ssim_fused_kernel(const float* __restrict__ x,
                       const float* __restrict__ y,
                       float* __restrict__ out) {
    const int tid = threadIdx.x;
    const int c0  = (blockIdx.x * TPB + tid) * CPT;
    const int img = blockIdx.z;
    const int r0  = blockIdx.y * ROWS_PER_STRIP;

    const float* xp = x + (size_t)img * W * H;
    const float* yp = y + (size_t)img * W * H;

    const uint64_t C1S  = pk(81.0f * 1e-4f, 81.0f * 1e-4f);
    const uint64_t C2S  = pk(81.0f * 9e-4f, 81.0f * 9e-4f);
    const uint64_t EPSS = pk(6.561e-5f, 6.561e-5f);
    const uint64_t TWO  = pk(2.0f, 2.0f);
    const uint64_t NINE = pk(9.0f, 9.0f);

    // Prologue: A = h(r0-1) + h(r0), B = h(r0)
    HRow A0, B0;
    {
        Raw wm1 = load_raw(xp, yp, r0 - 1, c0);
        Raw w0  = load_raw(xp, yp, r0,     c0);
        HRow hm1;
        hrow_from(wm1, hm1);
        hrow_from(w0, B0);
#pragma unroll
        for (int i = 0; i < 8; ++i) A0.v[i] = f2add(hm1.v[i], B0.v[i]);
    }

    float acc = 0.0f;

    // Software pipeline: raw row (r+1) is loaded one full step before its math.
    Raw ra = load_raw(xp, yp, r0 + 1, c0);

#pragma unroll 1
    for (int rr = 0; rr < ROWS_PER_STRIP; rr += 2) {
        Raw rb = load_raw(xp, yp, r0 + rr + 2, c0);   // prefetch next
        HRow N1;
        hrow_from(ra, N1);
        HRow A1, B1;
        step_math(N1, A0, B0, A1, B1, C1S, C2S, EPSS, TWO, NINE, acc);

        Raw rc = load_raw(xp, yp, r0 + rr + 3, c0);   // prefetch next+1
        HRow N2;
        hrow_from(rb, N2);
        step_math(N2, A1, B1, A0, B0, C1S, C2S, EPSS, TWO, NINE, acc);

        ra = rc;
    }

    // block reduction (float)
    for (int off = 16; off > 0; off >>= 1)
        acc += __shfl_down_sync(0xFFFFFFFFu, acc, off);

    __shared__ float warp_sums[TPB / 32];
    const int lane = tid & 31;
    const int wid  = tid >> 5;
    if (lane == 0) warp_sums[wid] = acc;
    __syncthreads();

    __shared__ bool is_last;
    if (tid == 0) {
        float v = warp_sums[0] + warp_sums[1] + warp_sums[2] + warp_sums[3];
        const int blin = (blockIdx.z * gridDim.y + blockIdx.y) * gridDim.x + blockIdx.x;
        g_partials[blin] = v;
        __threadfence();
        unsigned int prev = atomicAdd(&g_count, 1u);
        is_last = (prev == NBLOCKS - 1);
        if (is_last) g_count = 0;   // reset for next graph replay
    }
    __syncthreads();

    if (is_last) {
        __threadfence();
        double s = 0.0;
        for (int i = tid; i < NBLOCKS; i += TPB)
            s += (double)g_partials[i];

        for (int off = 16; off > 0; off >>= 1)
            s += __shfl_down_sync(0xFFFFFFFFu, s, off);

        __shared__ double dsum[TPB / 32];
        if (lane == 0) dsum[wid] = s;
        __syncthreads();
        if (tid == 0) {
            double v = dsum[0] + dsum[1] + dsum[2] + dsum[3];
            out[0] = (float)(1.0 - v / NPIX);
        }
    }
}

extern "C" void kernel_launch(void* const* d_in, const int* in_sizes, int n_in,
                              void* d_out, int out_size) {
    const float* x = (const float*)d_in[0];
    const float* y = (const float*)d_in[1];
    float* out = (float*)d_out;

    dim3 grid(GRID_X, GRID_Y, NIMG);
    ssim_fused_kernel<<<grid, TPB>>>(x, y, out);
}

// round 10
// speedup vs baseline: 1.6266x; 1.6266x over previous
#include <cuda_runtime.h>
#include <cstdint>

// SSIM loss fused single-pass: packed f32x2, 4 cols/thread, scaled-by-81
// identity, software-pipelined row loads, 64-row strips (single wave).
// Natural register allocation (no forced occupancy). (32,1,1024,1024) -> 1 float.

#define W 1024
#define H 1024
#define NIMG 32
#define TPB 128
#define CPT 4
#define COLS_PER_BLOCK (TPB * CPT)          // 512
#define GRID_X (W / COLS_PER_BLOCK)         // 2
#define ROWS_PER_STRIP 64
#define GRID_Y (H / ROWS_PER_STRIP)         // 16
#define NBLOCKS (GRID_X * GRID_Y * NIMG)    // 1024
#define NPIX ((double)NIMG * W * H)

__device__ float g_partials[NBLOCKS];
__device__ unsigned int g_count = 0;

// ---- packed f32x2 helpers (sm_103a) ----
__device__ __forceinline__ uint64_t pk(float lo, float hi) {
    uint64_t r;
    asm("mov.b64 %0, {%1, %2};" : "=l"(r) : "f"(lo), "f"(hi));
    return r;
}
__device__ __forceinline__ void upk(uint64_t v, float& lo, float& hi) {
    asm("mov.b64 {%0, %1}, %2;" : "=f"(lo), "=f"(hi) : "l"(v));
}
__device__ __forceinline__ uint64_t f2add(uint64_t a, uint64_t b) {
    uint64_t r;
    asm("add.rn.f32x2 %0, %1, %2;" : "=l"(r) : "l"(a), "l"(b));
    return r;
}
__device__ __forceinline__ uint64_t f2mul(uint64_t a, uint64_t b) {
    uint64_t r;
    asm("mul.rn.f32x2 %0, %1, %2;" : "=l"(r) : "l"(a), "l"(b));
    return r;
}
__device__ __forceinline__ uint64_t f2fma(uint64_t a, uint64_t b, uint64_t c) {
    uint64_t r;
    asm("fma.rn.f32x2 %0, %1, %2, %3;" : "=l"(r) : "l"(a), "l"(b), "l"(c));
    return r;
}
// packed negate: flip both sign bits (alu op, 64-bit immediate, no const reg)
__device__ __forceinline__ uint64_t f2neg(uint64_t a) {
    uint64_t r;
    asm("xor.b64 %0, %1, 0x8000000080000000;" : "=l"(r) : "l"(a));
    return r;
}

struct HRow { uint64_t v[8]; };  // [0,1]=hx [2,3]=hy [4,5]=h(x^2+y^2) [6,7]=h(xy)
struct Raw  { float4 vx, vy; float xl, xr, yl, yr; };

__device__ __forceinline__ Raw load_raw(const float* __restrict__ xp,
                                        const float* __restrict__ yp,
                                        int r, int c0) {
    Raw w;
    if ((unsigned)r < (unsigned)H) {
        const int base = r * W + c0;
        w.vx = *reinterpret_cast<const float4*>(xp + base);
        w.vy = *reinterpret_cast<const float4*>(yp + base);
        w.xl = (c0 > 0)     ? xp[base - 1] : 0.0f;
        w.xr = (c0 + 4 < W) ? xp[base + 4] : 0.0f;
        w.yl = (c0 > 0)     ? yp[base - 1] : 0.0f;
        w.yr = (c0 + 4 < W) ? yp[base + 4] : 0.0f;
    } else {
        w.vx = make_float4(0.f, 0.f, 0.f, 0.f);
        w.vy = make_float4(0.f, 0.f, 0.f, 0.f);
        w.xl = w.xr = w.yl = w.yr = 0.0f;
    }
    return w;
}

__device__ __forceinline__ void hrow_from(const Raw& w, HRow& h) {
    uint64_t PA0 = pk(w.xl, w.vx.x),   MA0 = pk(w.vx.x, w.vx.y);
    uint64_t PA1 = pk(w.vx.y, w.vx.z), MA1 = pk(w.vx.z, w.vx.w);
    uint64_t PA2 = pk(w.vx.w, w.xr);
    uint64_t PB0 = pk(w.yl, w.vy.x),   MB0 = pk(w.vy.x, w.vy.y);
    uint64_t PB1 = pk(w.vy.y, w.vy.z), MB1 = pk(w.vy.z, w.vy.w);
    uint64_t PB2 = pk(w.vy.w, w.yr);

    uint64_t S0  = f2fma(PA0, PA0, f2mul(PB0, PB0));
    uint64_t S1  = f2fma(PA1, PA1, f2mul(PB1, PB1));
    uint64_t S2  = f2fma(PA2, PA2, f2mul(PB2, PB2));
    uint64_t SM0 = f2fma(MA0, MA0, f2mul(MB0, MB0));
    uint64_t SM1 = f2fma(MA1, MA1, f2mul(MB1, MB1));
    uint64_t Q0  = f2mul(PA0, PB0);
    uint64_t Q1  = f2mul(PA1, PB1);
    uint64_t Q2  = f2mul(PA2, PB2);
    uint64_t QM0 = f2mul(MA0, MB0);
    uint64_t QM1 = f2mul(MA1, MB1);

    h.v[0] = f2add(f2add(PA0, MA0), PA1);
    h.v[1] = f2add(f2add(PA1, MA1), PA2);
    h.v[2] = f2add(f2add(PB0, MB0), PB1);
    h.v[3] = f2add(f2add(PB1, MB1), PB2);
    h.v[4] = f2add(f2add(S0, SM0), S1);
    h.v[5] = f2add(f2add(S1, SM1), S2);
    h.v[6] = f2add(f2add(Q0, QM0), Q1);
    h.v[7] = f2add(f2add(Q1, QM1), Q2);
}

// Consumes N (h of row r+1): S = A + N -> ssim; Aout = B + N; Bout = N.
__device__ __forceinline__ void step_math(const HRow& N,
                                          const HRow& A, const HRow& B,
                                          HRow& Aout, HRow& Bout,
                                          uint64_t C1S, uint64_t C2S,
                                          uint64_t EPSS, uint64_t TWO,
                                          uint64_t NINE, float& acc) {
    uint64_t S[8];
#pragma unroll
    for (int i = 0; i < 8; ++i) S[i] = f2add(A.v[i], N.v[i]);

#pragma unroll
    for (int half = 0; half < 2; ++half) {
        uint64_t sx  = S[half];
        uint64_t sy  = S[2 + half];
        uint64_t sss = S[4 + half];
        uint64_t sxy = S[6 + half];

        uint64_t ab  = f2mul(sx, sy);
        uint64_t t2  = f2fma(sx, sx, f2mul(sy, sy));
        uint64_t Aq  = f2fma(ab, TWO, C1S);                    // 2ab + 81C1
        uint64_t u   = f2fma(sxy, NINE, f2neg(ab));            // 9Sxy - ab
        uint64_t Bq  = f2fma(u, TWO, C2S);                     // 18Sxy - 2ab + 81C2
        uint64_t Cq  = f2add(t2, C1S);                         // t2 + 81C1
        uint64_t Dq  = f2add(f2fma(sss, NINE, C2S), f2neg(t2));// 9Sss - t2 + 81C2
        uint64_t num = f2mul(Aq, Bq);
        uint64_t den = f2fma(Cq, Dq, EPSS);

        float n0, n1, d0, d1;
        upk(num, n0, n1);
        upk(den, d0, d1);
        acc += __fdividef(fmaf(n0, d1, n1 * d0), d0 * d1);
    }

#pragma unroll
    for (int i = 0; i < 8; ++i) Aout.v[i] = f2add(B.v[i], N.v[i]);
    Bout = N;
}

__global__ __launch_bounds__(TPB)
void ssim_fused_kernel(const float* __restrict__ x,
                       const float* __restrict__ y,
                       float* __restrict__ out) {
    const int tid = threadIdx.x;
    const int c0  = (blockIdx.x * TPB + tid) * CPT;
    const int img = blockIdx.z;
    const int r0  = blockIdx.y * ROWS_PER_STRIP;

    const float* xp = x + (size_t)img * W * H;
    const float* yp = y + (size_t)img * W * H;

    const uint64_t C1S  = pk(81.0f * 1e-4f, 81.0f * 1e-4f);
    const uint64_t C2S  = pk(81.0f * 9e-4f, 81.0f * 9e-4f);
    const uint64_t EPSS = pk(6.561e-5f, 6.561e-5f);
    const uint64_t TWO  = pk(2.0f, 2.0f);
    const uint64_t NINE = pk(9.0f, 9.0f);

    // Prologue: A = h(r0-1) + h(r0), B = h(r0)
    HRow A0, B0;
    {
        Raw wm1 = load_raw(xp, yp, r0 - 1, c0);
        Raw w0  = load_raw(xp, yp, r0,     c0);
        HRow hm1;
        hrow_from(wm1, hm1);
        hrow_from(w0, B0);
#pragma unroll
        for (int i = 0; i < 8; ++i) A0.v[i] = f2add(hm1.v[i], B0.v[i]);
    }

    float acc = 0.0f;

    // Software pipeline: raw row (r+1) loaded one full step ahead of its math.
    Raw ra = load_raw(xp, yp, r0 + 1, c0);

#pragma unroll 1
    for (int rr = 0; rr < ROWS_PER_STRIP; rr += 2) {
        Raw rb = load_raw(xp, yp, r0 + rr + 2, c0);   // prefetch next
        HRow N1;
        hrow_from(ra, N1);
        HRow A1, B1;
        step_math(N1, A0, B0, A1, B1, C1S, C2S, EPSS, TWO, NINE, acc);

        Raw rc = load_raw(xp, yp, r0 + rr + 3, c0);   // prefetch next+1
        HRow N2;
        hrow_from(rb, N2);
        step_math(N2, A1, B1, A0, B0, C1S, C2S, EPSS, TWO, NINE, acc);

        ra = rc;
    }

    // block reduction (float)
    for (int off = 16; off > 0; off >>= 1)
        acc += __shfl_down_sync(0xFFFFFFFFu, acc, off);

    __shared__ float warp_sums[TPB / 32];
    const int lane = tid & 31;
    const int wid  = tid >> 5;
    if (lane == 0) warp_sums[wid] = acc;
    __syncthreads();

    __shared__ bool is_last;
    if (tid == 0) {
        float v = warp_sums[0] + warp_sums[1] + warp_sums[2] + warp_sums[3];
        const int blin = (blockIdx.z * gridDim.y + blockIdx.y) * gridDim.x + blockIdx.x;
        g_partials[blin] = v;
        __threadfence();
        unsigned int prev = atomicAdd(&g_count, 1u);
        is_last = (prev == NBLOCKS - 1);
        if (is_last) g_count = 0;   // reset for next graph replay
    }
    __syncthreads();

    if (is_last) {
        __threadfence();
        double s = 0.0;
        for (int i = tid; i < NBLOCKS; i += TPB)
            s += (double)g_partials[i];

        for (int off = 16; off > 0; off >>= 1)
            s += __shfl_down_sync(0xFFFFFFFFu, s, off);

        __shared__ double dsum[TPB / 32];
        if (lane == 0) dsum[wid] = s;
        __syncthreads();
        if (tid == 0) {
            double v = dsum[0] + dsum[1] + dsum[2] + dsum[3];
            out[0] = (float)(1.0 - v / NPIX);
        }
    }
}

extern "C" void kernel_launch(void* const* d_in, const int* in_sizes, int n_in,
                              void* d_out, int out_size) {
    const float* x = (const float*)d_in[0];
    const float* y = (const float*)d_in[1];
    float* out = (float*)d_out;

    dim3 grid(GRID_X, GRID_Y, NIMG);
    ssim_fused_kernel<<<grid, TPB>>>(x, y, out);
}